// round 3
// baseline (speedup 1.0000x reference)
#include <cuda_runtime.h>

// CurrentFactorCell, HBM-bound streaming elementwise.
//   out_re = cRR*zr*gr + cII*zi*gi + b0,  cRR = s0+m0, cII = m0-s0
//   out_im = cRI*zr*gi + cIR*zi*gr + b1,  cRI = s1-m1, cIR = s1+m1
// 8 elements per thread (2x float4 per stream), streaming cache hints.

__device__ __forceinline__ float4 ldcs4(const float4* p) { return __ldcs(p); }

__global__ void __launch_bounds__(256)
cfc_kernel(const float4* __restrict__ zr4,
           const float4* __restrict__ zi4,
           const float4* __restrict__ g4,     // interleaved (re,im) pairs
           const float*  __restrict__ scale,
           const float*  __restrict__ mix,
           const float*  __restrict__ bias,
           float4* __restrict__ out_re4,
           float4* __restrict__ out_im4,
           int n4)
{
    int t = blockIdx.x * blockDim.x + threadIdx.x;
    int i0 = 2 * t;                   // first float4 index
    if (i0 >= n4) return;

    float s0 = __ldg(&scale[0]), s1 = __ldg(&scale[1]);
    float m0 = __ldg(&mix[0]),   m1 = __ldg(&mix[1]);
    float b0 = __ldg(&bias[0]),  b1 = __ldg(&bias[1]);
    float cRR = s0 + m0;
    float cII = m0 - s0;
    float cRI = s1 - m1;
    float cIR = s1 + m1;

    // Front-batch all 8 loads (2 iterations x {zr, zi, ga, gb}) for max MLP.
    float4 zrA = ldcs4(zr4 + i0);
    float4 zrB = ldcs4(zr4 + i0 + 1);
    float4 ziA = ldcs4(zi4 + i0);
    float4 ziB = ldcs4(zi4 + i0 + 1);
    float4 gaA = ldcs4(g4 + 2 * i0 + 0);
    float4 gbA = ldcs4(g4 + 2 * i0 + 1);
    float4 gaB = ldcs4(g4 + 2 * i0 + 2);
    float4 gbB = ldcs4(g4 + 2 * i0 + 3);

    float4 oreA, oimA, oreB, oimB;

    oreA.x = fmaf(cRR, zrA.x * gaA.x, fmaf(cII, ziA.x * gaA.y, b0));
    oimA.x = fmaf(cRI, zrA.x * gaA.y, fmaf(cIR, ziA.x * gaA.x, b1));
    oreA.y = fmaf(cRR, zrA.y * gaA.z, fmaf(cII, ziA.y * gaA.w, b0));
    oimA.y = fmaf(cRI, zrA.y * gaA.w, fmaf(cIR, ziA.y * gaA.z, b1));
    oreA.z = fmaf(cRR, zrA.z * gbA.x, fmaf(cII, ziA.z * gbA.y, b0));
    oimA.z = fmaf(cRI, zrA.z * gbA.y, fmaf(cIR, ziA.z * gbA.x, b1));
    oreA.w = fmaf(cRR, zrA.w * gbA.z, fmaf(cII, ziA.w * gbA.w, b0));
    oimA.w = fmaf(cRI, zrA.w * gbA.w, fmaf(cIR, ziA.w * gbA.z, b1));

    oreB.x = fmaf(cRR, zrB.x * gaB.x, fmaf(cII, ziB.x * gaB.y, b0));
    oimB.x = fmaf(cRI, zrB.x * gaB.y, fmaf(cIR, ziB.x * gaB.x, b1));
    oreB.y = fmaf(cRR, zrB.y * gaB.z, fmaf(cII, ziB.y * gaB.w, b0));
    oimB.y = fmaf(cRI, zrB.y * gaB.w, fmaf(cIR, ziB.y * gaB.z, b1));
    oreB.z = fmaf(cRR, zrB.z * gbB.x, fmaf(cII, ziB.z * gbB.y, b0));
    oimB.z = fmaf(cRI, zrB.z * gbB.y, fmaf(cIR, ziB.z * gbB.x, b1));
    oreB.w = fmaf(cRR, zrB.w * gbB.z, fmaf(cII, ziB.w * gbB.w, b0));
    oimB.w = fmaf(cRI, zrB.w * gbB.w, fmaf(cIR, ziB.w * gbB.z, b1));

    __stcs(out_re4 + i0,     oreA);
    __stcs(out_re4 + i0 + 1, oreB);
    __stcs(out_im4 + i0,     oimA);
    __stcs(out_im4 + i0 + 1, oimB);
}

extern "C" void kernel_launch(void* const* d_in, const int* in_sizes, int n_in,
                              void* d_out, int out_size)
{
    const float* z_re  = (const float*)d_in[0];
    const float* z_im  = (const float*)d_in[1];
    const float* gate  = (const float*)d_in[2];
    const float* scale = (const float*)d_in[3];
    const float* mix   = (const float*)d_in[4];
    const float* bias  = (const float*)d_in[5];

    int n = in_sizes[0];            // 8388608
    int n4 = n / 4;                 // float4 count per stream
    int threads = 256;
    int elems4_per_thread = 2;      // 8 scalars per thread
    int total_threads = n4 / elems4_per_thread;
    int blocks = (total_threads + threads - 1) / threads;

    float* out_re = (float*)d_out;
    float* out_im = (float*)d_out + n;

    cfc_kernel<<<blocks, threads>>>(
        (const float4*)z_re, (const float4*)z_im, (const float4*)gate,
        scale, mix, bias,
        (float4*)out_re, (float4*)out_im, n4);
}

// round 6
// speedup vs baseline: 1.0532x; 1.0532x over previous
#include <cuda_runtime.h>

// CurrentFactorCell, HBM-bound streaming elementwise.
//   out_re = cRR*zr*gr + cII*zi*gi + b0,  cRR = s0+m0, cII = m0-s0
//   out_im = cRI*zr*gi + cIR*zi*gr + b1,  cRI = s1-m1, cIR = s1+m1
// R1 structure (4 elems/thread, 32 regs, ~80% occ) + streaming stores.

__global__ void __launch_bounds__(256)
cfc_kernel(const float4* __restrict__ zr4,
           const float4* __restrict__ zi4,
           const float4* __restrict__ g4,     // interleaved (re,im) pairs
           const float*  __restrict__ scale,
           const float*  __restrict__ mix,
           const float*  __restrict__ bias,
           float4* __restrict__ out_re4,
           float4* __restrict__ out_im4,
           int n4)
{
    int i = blockIdx.x * blockDim.x + threadIdx.x;
    if (i >= n4) return;

    float s0 = __ldg(&scale[0]), s1 = __ldg(&scale[1]);
    float m0 = __ldg(&mix[0]),   m1 = __ldg(&mix[1]);
    float b0 = __ldg(&bias[0]),  b1 = __ldg(&bias[1]);
    float cRR = s0 + m0;   // coeff for zr*gr in out_re
    float cII = m0 - s0;   // coeff for zi*gi in out_re
    float cRI = s1 - m1;   // coeff for zr*gi in out_im
    float cIR = s1 + m1;   // coeff for zi*gr in out_im

    float4 zr = zr4[i];
    float4 zi = zi4[i];
    float4 ga = g4[2 * i + 0];   // (gr0, gi0, gr1, gi1)
    float4 gb = g4[2 * i + 1];   // (gr2, gi2, gr3, gi3)

    float4 ore, oim;
    ore.x = fmaf(cRR, zr.x * ga.x, fmaf(cII, zi.x * ga.y, b0));
    oim.x = fmaf(cRI, zr.x * ga.y, fmaf(cIR, zi.x * ga.x, b1));
    ore.y = fmaf(cRR, zr.y * ga.z, fmaf(cII, zi.y * ga.w, b0));
    oim.y = fmaf(cRI, zr.y * ga.w, fmaf(cIR, zi.y * ga.z, b1));
    ore.z = fmaf(cRR, zr.z * gb.x, fmaf(cII, zi.z * gb.y, b0));
    oim.z = fmaf(cRI, zr.z * gb.y, fmaf(cIR, zi.z * gb.x, b1));
    ore.w = fmaf(cRR, zr.w * gb.z, fmaf(cII, zi.w * gb.w, b0));
    oim.w = fmaf(cRI, zr.w * gb.w, fmaf(cIR, zi.w * gb.z, b1));

    __stcs(out_re4 + i, ore);
    __stcs(out_im4 + i, oim);
}

extern "C" void kernel_launch(void* const* d_in, const int* in_sizes, int n_in,
                              void* d_out, int out_size)
{
    const float* z_re  = (const float*)d_in[0];
    const float* z_im  = (const float*)d_in[1];
    const float* gate  = (const float*)d_in[2];
    const float* scale = (const float*)d_in[3];
    const float* mix   = (const float*)d_in[4];
    const float* bias  = (const float*)d_in[5];

    int n = in_sizes[0];            // 8388608
    int n4 = n / 4;                 // 2097152, divisible by 256

    float* out_re = (float*)d_out;
    float* out_im = (float*)d_out + n;

    int threads = 256;
    int blocks = (n4 + threads - 1) / threads;   // 8192
    cfc_kernel<<<blocks, threads>>>(
        (const float4*)z_re, (const float4*)z_im, (const float4*)gate,
        scale, mix, bias,
        (float4*)out_re, (float4*)out_im, n4);
}